// round 2
// baseline (speedup 1.0000x reference)
#include <cuda_runtime.h>
#include <cuda_bf16.h>

#define M_NODES 50000
#define K_FEAT  256
#define N_HID   128
#define NUM_EDGES 1600000

// scratch for support = x @ W  (25.6 MB)
__device__ float g_support[M_NODES * N_HID];

// ---------------------------------------------------------------------------
// Kernel A: support = x @ W   (M=50000, K=256, N=128), fp32 smem-tiled
// block tile: 64 (M) x 128 (N), BK=16, 256 threads, each thread 4x8 outputs
// ---------------------------------------------------------------------------
__global__ __launch_bounds__(256) void gemm_kernel(
    const float* __restrict__ A,   // [M, 256]
    const float* __restrict__ B,   // [256, 128]
    float* __restrict__ C)         // [M, 128]
{
    __shared__ float As[16][64];
    __shared__ float Bs[16][128];

    const int tid = threadIdx.x;        // 0..255
    const int tx = tid & 15;            // 0..15  -> N direction (8 each)
    const int ty = tid >> 4;            // 0..15  -> M direction (4 each)
    const int m0 = blockIdx.x * 64;

    float acc[4][8];
    #pragma unroll
    for (int i = 0; i < 4; i++)
        #pragma unroll
        for (int j = 0; j < 8; j++)
            acc[i][j] = 0.f;

    for (int k0 = 0; k0 < K_FEAT; k0 += 16) {
        // load A tile: 64x16 = 1024 floats, 4 consecutive-k per thread
        {
            int idx = tid * 4;
            int ar = idx >> 4;          // 0..63
            int ac = idx & 15;          // 0,4,8,12
            float4 a = make_float4(0.f, 0.f, 0.f, 0.f);
            int gm = m0 + ar;
            if (gm < M_NODES)
                a = *(const float4*)(A + (size_t)gm * K_FEAT + k0 + ac);
            As[ac + 0][ar] = a.x;
            As[ac + 1][ar] = a.y;
            As[ac + 2][ar] = a.z;
            As[ac + 3][ar] = a.w;
        }
        // load B tile: 16x128 = 512 float4, 2 per thread
        {
            int f = tid * 2;
            #pragma unroll
            for (int i = 0; i < 2; i++) {
                int ff = f + i;
                int br = ff >> 5;           // 0..15
                int bc = (ff & 31) * 4;     // 0..124
                float4 b = *(const float4*)(B + (size_t)(k0 + br) * N_HID + bc);
                *(float4*)&Bs[br][bc] = b;
            }
        }
        __syncthreads();

        #pragma unroll
        for (int kk = 0; kk < 16; kk++) {
            float ra[4], rb[8];
            #pragma unroll
            for (int i = 0; i < 4; i++) ra[i] = As[kk][ty * 4 + i];
            #pragma unroll
            for (int j = 0; j < 8; j++) rb[j] = Bs[kk][tx * 8 + j];
            #pragma unroll
            for (int i = 0; i < 4; i++)
                #pragma unroll
                for (int j = 0; j < 8; j++)
                    acc[i][j] = fmaf(ra[i], rb[j], acc[i][j]);
        }
        __syncthreads();
    }

    #pragma unroll
    for (int i = 0; i < 4; i++) {
        int gm = m0 + ty * 4 + i;
        if (gm < M_NODES) {
            float* crow = C + (size_t)gm * N_HID + tx * 8;
            *(float4*)(crow + 0) = make_float4(acc[i][0], acc[i][1], acc[i][2], acc[i][3]);
            *(float4*)(crow + 4) = make_float4(acc[i][4], acc[i][5], acc[i][6], acc[i][7]);
        }
    }
}

// ---------------------------------------------------------------------------
// Kernel C: scatter-add. One warp per edge; lane l handles hid [4l, 4l+4).
// out[dst] += w * support[src]   (atomic)
// ---------------------------------------------------------------------------
__global__ __launch_bounds__(256) void scatter_kernel(
    const float* __restrict__ support,
    const int*   __restrict__ edge_index,  // [2, E]
    const float* __restrict__ edge_weight, // [E]
    float* __restrict__ out)               // [M, 128] pre-zeroed
{
    int gtid = blockIdx.x * blockDim.x + threadIdx.x;
    int e = gtid >> 5;
    int lane = gtid & 31;
    if (e >= NUM_EDGES) return;

    int src = __ldg(edge_index + e);
    int dst = __ldg(edge_index + NUM_EDGES + e);
    float w = __ldg(edge_weight + e);

    const float4* srow = (const float4*)(support + (size_t)src * N_HID) + lane;
    float* orow = out + (size_t)dst * N_HID + lane * 4;

    float4 v = *srow;
    atomicAdd(orow + 0, v.x * w);
    atomicAdd(orow + 1, v.y * w);
    atomicAdd(orow + 2, v.z * w);
    atomicAdd(orow + 3, v.w * w);
}

// ---------------------------------------------------------------------------
// Kernel D: per-row bias + relu + log_softmax, in place on out.
// One warp per row; lane holds 4 values (float4).
// ---------------------------------------------------------------------------
__global__ __launch_bounds__(256) void finalize_kernel(
    float* __restrict__ out,
    const float* __restrict__ bias)
{
    int gtid = blockIdx.x * blockDim.x + threadIdx.x;
    int row = gtid >> 5;
    int lane = gtid & 31;
    if (row >= M_NODES) return;

    float4 b = *(const float4*)(bias + lane * 4);
    float* rp = out + (size_t)row * N_HID + lane * 4;
    float4 v = *(float4*)rp;
    v.x = fmaxf(v.x + b.x, 0.f);
    v.y = fmaxf(v.y + b.y, 0.f);
    v.z = fmaxf(v.z + b.z, 0.f);
    v.w = fmaxf(v.w + b.w, 0.f);

    float m = fmaxf(fmaxf(v.x, v.y), fmaxf(v.z, v.w));
    #pragma unroll
    for (int off = 16; off > 0; off >>= 1)
        m = fmaxf(m, __shfl_xor_sync(0xFFFFFFFF, m, off));

    float s = __expf(v.x - m) + __expf(v.y - m) + __expf(v.z - m) + __expf(v.w - m);
    #pragma unroll
    for (int off = 16; off > 0; off >>= 1)
        s += __shfl_xor_sync(0xFFFFFFFF, s, off);

    float lse = m + __logf(s);
    v.x -= lse; v.y -= lse; v.z -= lse; v.w -= lse;
    *(float4*)rp = v;
}

// ---------------------------------------------------------------------------
extern "C" void kernel_launch(void* const* d_in, const int* in_sizes, int n_in,
                              void* d_out, int out_size)
{
    const float* x      = (const float*)d_in[0];  // [50000, 256]
    const float* weight = (const float*)d_in[1];  // [256, 128]
    const float* bias   = (const float*)d_in[2];  // [128]
    const int*   eidx   = (const int*)  d_in[3];  // [2, 1600000]
    const float* ew     = (const float*)d_in[4];  // [1600000]
    float* out = (float*)d_out;                   // [50000, 128]

    float* support;
    cudaGetSymbolAddress((void**)&support, g_support);

    // A: GEMM
    gemm_kernel<<<(M_NODES + 63) / 64, 256>>>(x, weight, support);

    // B: zero the accumulation target
    cudaMemsetAsync(d_out, 0, (size_t)M_NODES * N_HID * sizeof(float));

    // C: scatter-add over edges (warp per edge)
    {
        long long threads = (long long)NUM_EDGES * 32;
        int blocks = (int)((threads + 255) / 256);
        scatter_kernel<<<blocks, 256>>>(support, eidx, ew, out);
    }

    // D: bias + relu + log_softmax (warp per row)
    {
        long long threads = (long long)M_NODES * 32;
        int blocks = (int)((threads + 255) / 256);
        finalize_kernel<<<blocks, 256>>>(out, bias);
    }
}

// round 4
// speedup vs baseline: 1.9588x; 1.9588x over previous
#include <cuda_runtime.h>
#include <cuda_bf16.h>

#define M_NODES 50000
#define K_FEAT  256
#define N_HID   128
#define NUM_EDGES 1600000

// scratch for support = x @ W  (25.6 MB)
__device__ float g_support[M_NODES * N_HID];

// ---------------------------------------------------------------------------
// Kernel A: support = x @ W   (M=50000, K=256, N=128), fp32 smem-tiled
// block tile: 128 (M) x 128 (N), BK=8, 256 threads, 8x8 outputs per thread
// ---------------------------------------------------------------------------
__global__ __launch_bounds__(256) void gemm_kernel(
    const float* __restrict__ A,   // [M, 256]
    const float* __restrict__ B,   // [256, 128]
    float* __restrict__ C)         // [M, 128]
{
    __shared__ float As[8][128];   // k-major (transposed A tile)
    __shared__ float Bs[8][128];

    const int tid = threadIdx.x;        // 0..255
    const int tx = tid & 15;            // 0..15  -> N direction (8 each)
    const int ty = tid >> 4;            // 0..15  -> M direction (8 each)
    const int m0 = blockIdx.x * 128;

    float acc[8][8];
    #pragma unroll
    for (int i = 0; i < 8; i++)
        #pragma unroll
        for (int j = 0; j < 8; j++)
            acc[i][j] = 0.f;

    for (int k0 = 0; k0 < K_FEAT; k0 += 8) {
        // load A tile: 128 rows x 8 k -> store transposed. 1024 floats, 4/thread
        {
            int idx = tid * 4;
            int ar = idx >> 3;          // 0..127 (row within tile)
            int ac = idx & 7;           // 0 or 4 (k within tile)
            float4 a = make_float4(0.f, 0.f, 0.f, 0.f);
            int gm = m0 + ar;
            if (gm < M_NODES)
                a = *(const float4*)(A + (size_t)gm * K_FEAT + k0 + ac);
            As[ac + 0][ar] = a.x;
            As[ac + 1][ar] = a.y;
            As[ac + 2][ar] = a.z;
            As[ac + 3][ar] = a.w;
        }
        // load B tile: 8 k x 128 n. 1024 floats, 4/thread
        {
            int br = tid >> 5;              // 0..7
            int bc = (tid & 31) * 4;        // 0..124
            float4 b = *(const float4*)(B + (size_t)(k0 + br) * N_HID + bc);
            *(float4*)&Bs[br][bc] = b;
        }
        __syncthreads();

        #pragma unroll
        for (int kk = 0; kk < 8; kk++) {
            float ra[8], rb[8];
            #pragma unroll
            for (int i = 0; i < 8; i++) ra[i] = As[kk][ty * 8 + i];
            #pragma unroll
            for (int j = 0; j < 8; j++) rb[j] = Bs[kk][tx * 8 + j];
            #pragma unroll
            for (int i = 0; i < 8; i++)
                #pragma unroll
                for (int j = 0; j < 8; j++)
                    acc[i][j] = fmaf(ra[i], rb[j], acc[i][j]);
        }
        __syncthreads();
    }

    #pragma unroll
    for (int i = 0; i < 8; i++) {
        int gm = m0 + ty * 8 + i;
        if (gm < M_NODES) {
            float* crow = C + (size_t)gm * N_HID + tx * 8;
            *(float4*)(crow + 0) = make_float4(acc[i][0], acc[i][1], acc[i][2], acc[i][3]);
            *(float4*)(crow + 4) = make_float4(acc[i][4], acc[i][5], acc[i][6], acc[i][7]);
        }
    }
}

// ---------------------------------------------------------------------------
// Kernel C: scatter-add. One warp per edge; lane l handles hid [4l, 4l+4).
// out[dst] += w * support[src]  via vector red.global.add.v4.f32 (sm_90+)
// ---------------------------------------------------------------------------
__global__ __launch_bounds__(256) void scatter_kernel(
    const float* __restrict__ support,
    const int*   __restrict__ edge_index,  // [2, E]
    const float* __restrict__ edge_weight, // [E]
    float* __restrict__ out)               // [M, 128] pre-zeroed
{
    int gtid = blockIdx.x * blockDim.x + threadIdx.x;
    int e = gtid >> 5;
    int lane = gtid & 31;
    if (e >= NUM_EDGES) return;

    int src = __ldg(edge_index + e);
    int dst = __ldg(edge_index + NUM_EDGES + e);
    float w = __ldg(edge_weight + e);

    float4 v = *(const float4*)(support + (size_t)src * N_HID + lane * 4);
    float* orow = out + (size_t)dst * N_HID + lane * 4;

    asm volatile(
        "red.global.add.v4.f32 [%0], {%1, %2, %3, %4};"
        :: "l"(orow), "f"(v.x * w), "f"(v.y * w), "f"(v.z * w), "f"(v.w * w)
        : "memory");
}

// ---------------------------------------------------------------------------
// Kernel D: per-row bias + relu + log_softmax, in place on out.
// One warp per row; lane holds 4 values (float4).
// ---------------------------------------------------------------------------
__global__ __launch_bounds__(256) void finalize_kernel(
    float* __restrict__ out,
    const float* __restrict__ bias)
{
    int gtid = blockIdx.x * blockDim.x + threadIdx.x;
    int row = gtid >> 5;
    int lane = gtid & 31;
    if (row >= M_NODES) return;

    float4 b = *(const float4*)(bias + lane * 4);
    float* rp = out + (size_t)row * N_HID + lane * 4;
    float4 v = *(float4*)rp;
    v.x = fmaxf(v.x + b.x, 0.f);
    v.y = fmaxf(v.y + b.y, 0.f);
    v.z = fmaxf(v.z + b.z, 0.f);
    v.w = fmaxf(v.w + b.w, 0.f);

    float m = fmaxf(fmaxf(v.x, v.y), fmaxf(v.z, v.w));
    #pragma unroll
    for (int off = 16; off > 0; off >>= 1)
        m = fmaxf(m, __shfl_xor_sync(0xFFFFFFFF, m, off));

    float s = __expf(v.x - m) + __expf(v.y - m) + __expf(v.z - m) + __expf(v.w - m);
    #pragma unroll
    for (int off = 16; off > 0; off >>= 1)
        s += __shfl_xor_sync(0xFFFFFFFF, s, off);

    float lse = m + __logf(s);
    v.x -= lse; v.y -= lse; v.z -= lse; v.w -= lse;
    *(float4*)rp = v;
}

// ---------------------------------------------------------------------------
extern "C" void kernel_launch(void* const* d_in, const int* in_sizes, int n_in,
                              void* d_out, int out_size)
{
    const float* x      = (const float*)d_in[0];  // [50000, 256]
    const float* weight = (const float*)d_in[1];  // [256, 128]
    const float* bias   = (const float*)d_in[2];  // [128]
    const int*   eidx   = (const int*)  d_in[3];  // [2, 1600000]
    const float* ew     = (const float*)d_in[4];  // [1600000]
    float* out = (float*)d_out;                   // [50000, 128]

    float* support;
    cudaGetSymbolAddress((void**)&support, g_support);

    // A: GEMM
    gemm_kernel<<<(M_NODES + 127) / 128, 256>>>(x, weight, support);

    // B: zero the accumulation target
    cudaMemsetAsync(d_out, 0, (size_t)M_NODES * N_HID * sizeof(float));

    // C: scatter-add over edges (warp per edge)
    {
        long long threads = (long long)NUM_EDGES * 32;
        int blocks = (int)((threads + 255) / 256);
        scatter_kernel<<<blocks, 256>>>(support, eidx, ew, out);
    }

    // D: bias + relu + log_softmax (warp per row)
    {
        long long threads = (long long)M_NODES * 32;
        int blocks = (int)((threads + 255) / 256);
        finalize_kernel<<<blocks, 256>>>(out, bias);
    }
}

// round 5
// speedup vs baseline: 2.5218x; 1.2874x over previous
#include <cuda_runtime.h>
#include <cuda_bf16.h>
#include <cstdint>

#define M_NODES 50000
#define K_FEAT  256
#define N_HID   128
#define NUM_EDGES 1600000

// scratch for support = x @ W  (25.6 MB)
__device__ float g_support[M_NODES * N_HID];

// ---------------------------------------------------------------------------
// Kernel A: support = x @ W  via tf32 mma.sync (m16n8k8)
// block tile 128(M) x 128(N), BK=32, 256 threads (8 warps: 4M x 2N)
// warp tile 32(M) x 64(N): 2 x 8 mma tiles, acc[2][8][4]
// ---------------------------------------------------------------------------
#define A_STRIDE 36   // 128 rows x 32 k, padded (conflict-free frag loads)
#define B_STRIDE 136  // 32 k x 128 n, padded

__device__ __forceinline__ uint32_t f32_to_tf32(float f) {
    uint32_t r;
    asm("cvt.rna.tf32.f32 %0, %1;" : "=r"(r) : "f"(f));
    return r;
}

__global__ __launch_bounds__(256) void gemm_tf32_kernel(
    const float* __restrict__ A,   // [M, 256]
    const float* __restrict__ B,   // [256, 128]
    float* __restrict__ C)         // [M, 128]
{
    __shared__ uint32_t As[128 * A_STRIDE];
    __shared__ uint32_t Bs[32 * B_STRIDE];

    const int tid  = threadIdx.x;
    const int warp = tid >> 5;
    const int lane = tid & 31;
    const int warpM = warp >> 1;        // 0..3
    const int warpN = warp & 1;         // 0..1
    const int rbase = warpM * 32;
    const int nbase = warpN * 64;
    const int m0 = blockIdx.x * 128;

    const int qrow = lane >> 2;         // 0..7
    const int qcol = lane & 3;          // 0..3

    float acc[2][8][4];
    #pragma unroll
    for (int mt = 0; mt < 2; mt++)
        #pragma unroll
        for (int nt = 0; nt < 8; nt++)
            #pragma unroll
            for (int i = 0; i < 4; i++)
                acc[mt][nt][i] = 0.f;

    for (int k0g = 0; k0g < K_FEAT; k0g += 32) {
        // load A tile: 128 x 32 floats = 1024 float4, 4 per thread
        #pragma unroll
        for (int i = 0; i < 4; i++) {
            int f = tid + i * 256;
            int row = f >> 3;           // 0..127
            int c4  = (f & 7) * 4;      // 0..28
            float4 v = make_float4(0.f, 0.f, 0.f, 0.f);
            int gm = m0 + row;
            if (gm < M_NODES)
                v = *(const float4*)(A + (size_t)gm * K_FEAT + k0g + c4);
            uint32_t* p = &As[row * A_STRIDE + c4];
            p[0] = f32_to_tf32(v.x);
            p[1] = f32_to_tf32(v.y);
            p[2] = f32_to_tf32(v.z);
            p[3] = f32_to_tf32(v.w);
        }
        // load B tile: 32 x 128 floats = 1024 float4, 4 per thread
        #pragma unroll
        for (int i = 0; i < 4; i++) {
            int f = tid + i * 256;
            int row = f >> 5;           // 0..31
            int c4  = (f & 31) * 4;     // 0..124
            float4 v = *(const float4*)(B + (size_t)(k0g + row) * N_HID + c4);
            uint32_t* p = &Bs[row * B_STRIDE + c4];
            p[0] = f32_to_tf32(v.x);
            p[1] = f32_to_tf32(v.y);
            p[2] = f32_to_tf32(v.z);
            p[3] = f32_to_tf32(v.w);
        }
        __syncthreads();

        #pragma unroll
        for (int ks = 0; ks < 4; ks++) {
            const int k0 = ks * 8;
            // A fragments: 2 m-tiles
            uint32_t a[2][4];
            #pragma unroll
            for (int mt = 0; mt < 2; mt++) {
                int r = rbase + mt * 16 + qrow;
                a[mt][0] = As[(r    ) * A_STRIDE + k0 + qcol    ];
                a[mt][1] = As[(r + 8) * A_STRIDE + k0 + qcol    ];
                a[mt][2] = As[(r    ) * A_STRIDE + k0 + qcol + 4];
                a[mt][3] = As[(r + 8) * A_STRIDE + k0 + qcol + 4];
            }
            // B fragments: 8 n-tiles
            uint32_t b[8][2];
            #pragma unroll
            for (int nt = 0; nt < 8; nt++) {
                int c = nbase + nt * 8 + qrow;
                b[nt][0] = Bs[(k0 + qcol    ) * B_STRIDE + c];
                b[nt][1] = Bs[(k0 + qcol + 4) * B_STRIDE + c];
            }
            #pragma unroll
            for (int mt = 0; mt < 2; mt++)
                #pragma unroll
                for (int nt = 0; nt < 8; nt++)
                    asm volatile(
                        "mma.sync.aligned.m16n8k8.row.col.f32.tf32.tf32.f32 "
                        "{%0,%1,%2,%3}, {%4,%5,%6,%7}, {%8,%9}, {%0,%1,%2,%3};"
                        : "+f"(acc[mt][nt][0]), "+f"(acc[mt][nt][1]),
                          "+f"(acc[mt][nt][2]), "+f"(acc[mt][nt][3])
                        : "r"(a[mt][0]), "r"(a[mt][1]), "r"(a[mt][2]), "r"(a[mt][3]),
                          "r"(b[nt][0]), "r"(b[nt][1]));
        }
        __syncthreads();
    }

    // epilogue
    #pragma unroll
    for (int mt = 0; mt < 2; mt++) {
        int row0 = m0 + rbase + mt * 16 + qrow;
        #pragma unroll
        for (int nt = 0; nt < 8; nt++) {
            int col = nbase + nt * 8 + 2 * qcol;
            if (row0 < M_NODES)
                *(float2*)(C + (size_t)row0 * N_HID + col) =
                    make_float2(acc[mt][nt][0], acc[mt][nt][1]);
            if (row0 + 8 < M_NODES)
                *(float2*)(C + (size_t)(row0 + 8) * N_HID + col) =
                    make_float2(acc[mt][nt][2], acc[mt][nt][3]);
        }
    }
}

// ---------------------------------------------------------------------------
// Kernel C: scatter-add. One warp per edge; lane l handles hid [4l, 4l+4).
// out[dst] += w * support[src]  via vector red.global.add.v4.f32 (sm_90+)
// ---------------------------------------------------------------------------
__global__ __launch_bounds__(256) void scatter_kernel(
    const float* __restrict__ support,
    const int*   __restrict__ edge_index,  // [2, E]
    const float* __restrict__ edge_weight, // [E]
    float* __restrict__ out)               // [M, 128] pre-zeroed
{
    int gtid = blockIdx.x * blockDim.x + threadIdx.x;
    int e = gtid >> 5;
    int lane = gtid & 31;
    if (e >= NUM_EDGES) return;

    int src = __ldg(edge_index + e);
    int dst = __ldg(edge_index + NUM_EDGES + e);
    float w = __ldg(edge_weight + e);

    float4 v = *(const float4*)(support + (size_t)src * N_HID + lane * 4);
    float* orow = out + (size_t)dst * N_HID + lane * 4;

    asm volatile(
        "red.global.add.v4.f32 [%0], {%1, %2, %3, %4};"
        :: "l"(orow), "f"(v.x * w), "f"(v.y * w), "f"(v.z * w), "f"(v.w * w)
        : "memory");
}

// ---------------------------------------------------------------------------
// Kernel D: per-row bias + relu + log_softmax, in place on out.
// One warp per row; lane holds 4 values (float4).
// ---------------------------------------------------------------------------
__global__ __launch_bounds__(256) void finalize_kernel(
    float* __restrict__ out,
    const float* __restrict__ bias)
{
    int gtid = blockIdx.x * blockDim.x + threadIdx.x;
    int row = gtid >> 5;
    int lane = gtid & 31;
    if (row >= M_NODES) return;

    float4 b = *(const float4*)(bias + lane * 4);
    float* rp = out + (size_t)row * N_HID + lane * 4;
    float4 v = *(float4*)rp;
    v.x = fmaxf(v.x + b.x, 0.f);
    v.y = fmaxf(v.y + b.y, 0.f);
    v.z = fmaxf(v.z + b.z, 0.f);
    v.w = fmaxf(v.w + b.w, 0.f);

    float m = fmaxf(fmaxf(v.x, v.y), fmaxf(v.z, v.w));
    #pragma unroll
    for (int off = 16; off > 0; off >>= 1)
        m = fmaxf(m, __shfl_xor_sync(0xFFFFFFFF, m, off));

    float s = __expf(v.x - m) + __expf(v.y - m) + __expf(v.z - m) + __expf(v.w - m);
    #pragma unroll
    for (int off = 16; off > 0; off >>= 1)
        s += __shfl_xor_sync(0xFFFFFFFF, s, off);

    float lse = m + __logf(s);
    v.x -= lse; v.y -= lse; v.z -= lse; v.w -= lse;
    *(float4*)rp = v;
}

// ---------------------------------------------------------------------------
extern "C" void kernel_launch(void* const* d_in, const int* in_sizes, int n_in,
                              void* d_out, int out_size)
{
    const float* x      = (const float*)d_in[0];  // [50000, 256]
    const float* weight = (const float*)d_in[1];  // [256, 128]
    const float* bias   = (const float*)d_in[2];  // [128]
    const int*   eidx   = (const int*)  d_in[3];  // [2, 1600000]
    const float* ew     = (const float*)d_in[4];  // [1600000]
    float* out = (float*)d_out;                   // [50000, 128]

    float* support;
    cudaGetSymbolAddress((void**)&support, g_support);

    // A: GEMM (tf32 tensor cores)
    gemm_tf32_kernel<<<(M_NODES + 127) / 128, 256>>>(x, weight, support);

    // B: zero the accumulation target
    cudaMemsetAsync(d_out, 0, (size_t)M_NODES * N_HID * sizeof(float));

    // C: scatter-add over edges (warp per edge)
    {
        long long threads = (long long)NUM_EDGES * 32;
        int blocks = (int)((threads + 255) / 256);
        scatter_kernel<<<blocks, 256>>>(support, eidx, ew, out);
    }

    // D: bias + relu + log_softmax (warp per row)
    {
        long long threads = (long long)M_NODES * 32;
        int blocks = (int)((threads + 255) / 256);
        finalize_kernel<<<blocks, 256>>>(out, bias);
    }
}

// round 6
// speedup vs baseline: 3.9107x; 1.5507x over previous
#include <cuda_runtime.h>
#include <cuda_bf16.h>
#include <cstdint>

#define M_NODES 50000
#define K_FEAT  256
#define N_HID   128
#define NUM_EDGES 1600000
#define SCAN_NB  ((M_NODES + 255) / 256)   // 196

// ---------------------------------------------------------------------------
// Device scratch (static; no runtime allocation)
// ---------------------------------------------------------------------------
__device__ float g_support[M_NODES * N_HID];   // 25.6 MB
__device__ int   g_deg[M_NODES];
__device__ int   g_start[M_NODES];
__device__ int   g_cursor[M_NODES];
__device__ int   g_bsum[SCAN_NB];
__device__ int   g_esrc[NUM_EDGES];
__device__ float g_ewp[NUM_EDGES];

// ---------------------------------------------------------------------------
// Kernel A: support = x @ W  via tf32 mma.sync (m16n8k8)  [unchanged from R5]
// ---------------------------------------------------------------------------
#define A_STRIDE 36
#define B_STRIDE 136

__device__ __forceinline__ uint32_t f32_to_tf32(float f) {
    uint32_t r;
    asm("cvt.rna.tf32.f32 %0, %1;" : "=r"(r) : "f"(f));
    return r;
}

__global__ __launch_bounds__(256) void gemm_tf32_kernel(
    const float* __restrict__ A,
    const float* __restrict__ B,
    float* __restrict__ C)
{
    __shared__ uint32_t As[128 * A_STRIDE];
    __shared__ uint32_t Bs[32 * B_STRIDE];

    const int tid  = threadIdx.x;
    const int warp = tid >> 5;
    const int lane = tid & 31;
    const int warpM = warp >> 1;
    const int warpN = warp & 1;
    const int rbase = warpM * 32;
    const int nbase = warpN * 64;
    const int m0 = blockIdx.x * 128;

    const int qrow = lane >> 2;
    const int qcol = lane & 3;

    float acc[2][8][4];
    #pragma unroll
    for (int mt = 0; mt < 2; mt++)
        #pragma unroll
        for (int nt = 0; nt < 8; nt++)
            #pragma unroll
            for (int i = 0; i < 4; i++)
                acc[mt][nt][i] = 0.f;

    for (int k0g = 0; k0g < K_FEAT; k0g += 32) {
        #pragma unroll
        for (int i = 0; i < 4; i++) {
            int f = tid + i * 256;
            int row = f >> 3;
            int c4  = (f & 7) * 4;
            float4 v = make_float4(0.f, 0.f, 0.f, 0.f);
            int gm = m0 + row;
            if (gm < M_NODES)
                v = *(const float4*)(A + (size_t)gm * K_FEAT + k0g + c4);
            uint32_t* p = &As[row * A_STRIDE + c4];
            p[0] = f32_to_tf32(v.x);
            p[1] = f32_to_tf32(v.y);
            p[2] = f32_to_tf32(v.z);
            p[3] = f32_to_tf32(v.w);
        }
        #pragma unroll
        for (int i = 0; i < 4; i++) {
            int f = tid + i * 256;
            int row = f >> 5;
            int c4  = (f & 31) * 4;
            float4 v = *(const float4*)(B + (size_t)(k0g + row) * N_HID + c4);
            uint32_t* p = &Bs[row * B_STRIDE + c4];
            p[0] = f32_to_tf32(v.x);
            p[1] = f32_to_tf32(v.y);
            p[2] = f32_to_tf32(v.z);
            p[3] = f32_to_tf32(v.w);
        }
        __syncthreads();

        #pragma unroll
        for (int ks = 0; ks < 4; ks++) {
            const int k0 = ks * 8;
            uint32_t a[2][4];
            #pragma unroll
            for (int mt = 0; mt < 2; mt++) {
                int r = rbase + mt * 16 + qrow;
                a[mt][0] = As[(r    ) * A_STRIDE + k0 + qcol    ];
                a[mt][1] = As[(r + 8) * A_STRIDE + k0 + qcol    ];
                a[mt][2] = As[(r    ) * A_STRIDE + k0 + qcol + 4];
                a[mt][3] = As[(r + 8) * A_STRIDE + k0 + qcol + 4];
            }
            uint32_t b[8][2];
            #pragma unroll
            for (int nt = 0; nt < 8; nt++) {
                int c = nbase + nt * 8 + qrow;
                b[nt][0] = Bs[(k0 + qcol    ) * B_STRIDE + c];
                b[nt][1] = Bs[(k0 + qcol + 4) * B_STRIDE + c];
            }
            #pragma unroll
            for (int mt = 0; mt < 2; mt++)
                #pragma unroll
                for (int nt = 0; nt < 8; nt++)
                    asm volatile(
                        "mma.sync.aligned.m16n8k8.row.col.f32.tf32.tf32.f32 "
                        "{%0,%1,%2,%3}, {%4,%5,%6,%7}, {%8,%9}, {%0,%1,%2,%3};"
                        : "+f"(acc[mt][nt][0]), "+f"(acc[mt][nt][1]),
                          "+f"(acc[mt][nt][2]), "+f"(acc[mt][nt][3])
                        : "r"(a[mt][0]), "r"(a[mt][1]), "r"(a[mt][2]), "r"(a[mt][3]),
                          "r"(b[nt][0]), "r"(b[nt][1]));
        }
        __syncthreads();
    }

    #pragma unroll
    for (int mt = 0; mt < 2; mt++) {
        int row0 = m0 + rbase + mt * 16 + qrow;
        #pragma unroll
        for (int nt = 0; nt < 8; nt++) {
            int col = nbase + nt * 8 + 2 * qcol;
            if (row0 < M_NODES)
                *(float2*)(C + (size_t)row0 * N_HID + col) =
                    make_float2(acc[mt][nt][0], acc[mt][nt][1]);
            if (row0 + 8 < M_NODES)
                *(float2*)(C + (size_t)(row0 + 8) * N_HID + col) =
                    make_float2(acc[mt][nt][2], acc[mt][nt][3]);
        }
    }
}

// ---------------------------------------------------------------------------
// Binning kernels: build dst-sorted edge list
// ---------------------------------------------------------------------------
__global__ __launch_bounds__(256) void count_kernel(
    const int* __restrict__ edge_index)
{
    int e = blockIdx.x * blockDim.x + threadIdx.x;
    if (e >= NUM_EDGES) return;
    int dst = __ldg(edge_index + NUM_EDGES + e);
    atomicAdd(&g_deg[dst], 1);
}

// Stage 1: per-block exclusive scan of 256 degrees, write local-exclusive to
// g_start, block total to g_bsum.
__global__ __launch_bounds__(256) void scan1_kernel()
{
    __shared__ int sh[256];
    int i = blockIdx.x * 256 + threadIdx.x;
    int v = (i < M_NODES) ? g_deg[i] : 0;
    sh[threadIdx.x] = v;
    __syncthreads();
    // Hillis-Steele inclusive scan
    #pragma unroll
    for (int off = 1; off < 256; off <<= 1) {
        int t = (threadIdx.x >= off) ? sh[threadIdx.x - off] : 0;
        __syncthreads();
        sh[threadIdx.x] += t;
        __syncthreads();
    }
    if (i < M_NODES) g_start[i] = sh[threadIdx.x] - v;   // exclusive, local
    if (threadIdx.x == 255) g_bsum[blockIdx.x] = sh[255];
}

// Stage 2: single block exclusive scan of the block sums.
__global__ __launch_bounds__(256) void scan2_kernel()
{
    __shared__ int sh[256];
    int v = (threadIdx.x < SCAN_NB) ? g_bsum[threadIdx.x] : 0;
    sh[threadIdx.x] = v;
    __syncthreads();
    #pragma unroll
    for (int off = 1; off < 256; off <<= 1) {
        int t = (threadIdx.x >= off) ? sh[threadIdx.x - off] : 0;
        __syncthreads();
        sh[threadIdx.x] += t;
        __syncthreads();
    }
    if (threadIdx.x < SCAN_NB) g_bsum[threadIdx.x] = sh[threadIdx.x] - v;
}

// Stage 3: add block offsets; produce g_start (final) and g_cursor (working copy).
__global__ __launch_bounds__(256) void scan3_kernel()
{
    int i = blockIdx.x * 256 + threadIdx.x;
    if (i >= M_NODES) return;
    int s = g_start[i] + g_bsum[blockIdx.x];
    g_start[i]  = s;
    g_cursor[i] = s;
}

__global__ __launch_bounds__(256) void permute_kernel(
    const int* __restrict__ edge_index,
    const float* __restrict__ edge_weight)
{
    int e = blockIdx.x * blockDim.x + threadIdx.x;
    if (e >= NUM_EDGES) return;
    int src = __ldg(edge_index + e);
    int dst = __ldg(edge_index + NUM_EDGES + e);
    float w = __ldg(edge_weight + e);
    int p = atomicAdd(&g_cursor[dst], 1);
    g_esrc[p] = src;
    g_ewp[p]  = w;
}

// ---------------------------------------------------------------------------
// Aggregate + bias + relu + log_softmax, fused. One warp per dst row.
// Lane l owns hid channels [4l, 4l+4). Edge records batched 32-wide, coalesced,
// then shuffle-broadcast; gathers from support are coalesced 512B per edge.
// ---------------------------------------------------------------------------
__global__ __launch_bounds__(256) void aggregate_kernel(
    const float* __restrict__ support,
    const float* __restrict__ bias,
    float* __restrict__ out)
{
    int row  = blockIdx.x * 8 + (threadIdx.x >> 5);
    int lane = threadIdx.x & 31;
    if (row >= M_NODES) return;

    int start = g_start[row];
    int deg   = g_deg[row];
    int end   = start + deg;

    float4 acc = make_float4(0.f, 0.f, 0.f, 0.f);

    for (int base = start; base < end; base += 32) {
        int n = end - base;
        if (n > 32) n = 32;
        int   s = 0;
        float w = 0.f;
        if (lane < n) {
            s = __ldg(g_esrc + base + lane);
            w = __ldg(g_ewp  + base + lane);
        }
        for (int k = 0; k < n; k++) {
            int   sk = __shfl_sync(0xFFFFFFFF, s, k);
            float wk = __shfl_sync(0xFFFFFFFF, w, k);
            float4 v = *(const float4*)(support + (size_t)sk * N_HID + lane * 4);
            acc.x = fmaf(v.x, wk, acc.x);
            acc.y = fmaf(v.y, wk, acc.y);
            acc.z = fmaf(v.z, wk, acc.z);
            acc.w = fmaf(v.w, wk, acc.w);
        }
    }

    float4 b = *(const float4*)(bias + lane * 4);
    acc.x = fmaxf(acc.x + b.x, 0.f);
    acc.y = fmaxf(acc.y + b.y, 0.f);
    acc.z = fmaxf(acc.z + b.z, 0.f);
    acc.w = fmaxf(acc.w + b.w, 0.f);

    float m = fmaxf(fmaxf(acc.x, acc.y), fmaxf(acc.z, acc.w));
    #pragma unroll
    for (int off = 16; off > 0; off >>= 1)
        m = fmaxf(m, __shfl_xor_sync(0xFFFFFFFF, m, off));

    float ssum = __expf(acc.x - m) + __expf(acc.y - m) +
                 __expf(acc.z - m) + __expf(acc.w - m);
    #pragma unroll
    for (int off = 16; off > 0; off >>= 1)
        ssum += __shfl_xor_sync(0xFFFFFFFF, ssum, off);

    float lse = m + __logf(ssum);
    float4 r = make_float4(acc.x - lse, acc.y - lse, acc.z - lse, acc.w - lse);
    *(float4*)(out + (size_t)row * N_HID + lane * 4) = r;
}

// ---------------------------------------------------------------------------
extern "C" void kernel_launch(void* const* d_in, const int* in_sizes, int n_in,
                              void* d_out, int out_size)
{
    const float* x      = (const float*)d_in[0];
    const float* weight = (const float*)d_in[1];
    const float* bias   = (const float*)d_in[2];
    const int*   eidx   = (const int*)  d_in[3];
    const float* ew     = (const float*)d_in[4];
    float* out = (float*)d_out;

    float* support;
    cudaGetSymbolAddress((void**)&support, g_support);
    void* degp;
    cudaGetSymbolAddress(&degp, g_deg);

    const int EB = (NUM_EDGES + 255) / 256;

    // GEMM (independent of binning; runs first)
    gemm_tf32_kernel<<<(M_NODES + 127) / 128, 256>>>(x, weight, support);

    // Binning pipeline
    cudaMemsetAsync(degp, 0, M_NODES * sizeof(int));
    count_kernel<<<EB, 256>>>(eidx);
    scan1_kernel<<<SCAN_NB, 256>>>();
    scan2_kernel<<<1, 256>>>();
    scan3_kernel<<<SCAN_NB, 256>>>();
    permute_kernel<<<EB, 256>>>(eidx, ew);

    // Fused aggregate + bias + relu + log_softmax
    aggregate_kernel<<<(M_NODES + 7) / 8, 256>>>(support, bias, out);
}

// round 7
// speedup vs baseline: 4.4699x; 1.1430x over previous
#include <cuda_runtime.h>
#include <cuda_fp16.h>
#include <cstdint>

#define M_NODES 50000
#define K_FEAT  256
#define N_HID   128
#define NUM_EDGES 1600000
#define SCAN_NB  ((M_NODES + 255) / 256)   // 196

// ---------------------------------------------------------------------------
// Device scratch (static; no runtime allocation)
// ---------------------------------------------------------------------------
__device__ __half g_support[M_NODES * N_HID];  // 12.8 MB (fp16)
__device__ int   g_deg[M_NODES];
__device__ int   g_start[M_NODES];
__device__ int   g_cursor[M_NODES];
__device__ int   g_bsum[SCAN_NB];
__device__ int2  g_edge[NUM_EDGES];            // (src, bitcast(w))

// ---------------------------------------------------------------------------
// Kernel A: support = x @ W  via tf32 mma.sync (m16n8k8); fp16 epilogue
// ---------------------------------------------------------------------------
#define A_STRIDE 36
#define B_STRIDE 136

__device__ __forceinline__ uint32_t f32_to_tf32(float f) {
    uint32_t r;
    asm("cvt.rna.tf32.f32 %0, %1;" : "=r"(r) : "f"(f));
    return r;
}

__global__ __launch_bounds__(256) void gemm_tf32_kernel(
    const float* __restrict__ A,
    const float* __restrict__ B,
    __half* __restrict__ C)
{
    __shared__ uint32_t As[128 * A_STRIDE];
    __shared__ uint32_t Bs[32 * B_STRIDE];

    const int tid  = threadIdx.x;
    const int warp = tid >> 5;
    const int lane = tid & 31;
    const int warpM = warp >> 1;
    const int warpN = warp & 1;
    const int rbase = warpM * 32;
    const int nbase = warpN * 64;
    const int m0 = blockIdx.x * 128;

    const int qrow = lane >> 2;
    const int qcol = lane & 3;

    float acc[2][8][4];
    #pragma unroll
    for (int mt = 0; mt < 2; mt++)
        #pragma unroll
        for (int nt = 0; nt < 8; nt++)
            #pragma unroll
            for (int i = 0; i < 4; i++)
                acc[mt][nt][i] = 0.f;

    for (int k0g = 0; k0g < K_FEAT; k0g += 32) {
        #pragma unroll
        for (int i = 0; i < 4; i++) {
            int f = tid + i * 256;
            int row = f >> 3;
            int c4  = (f & 7) * 4;
            float4 v = make_float4(0.f, 0.f, 0.f, 0.f);
            int gm = m0 + row;
            if (gm < M_NODES)
                v = *(const float4*)(A + (size_t)gm * K_FEAT + k0g + c4);
            uint32_t* p = &As[row * A_STRIDE + c4];
            p[0] = f32_to_tf32(v.x);
            p[1] = f32_to_tf32(v.y);
            p[2] = f32_to_tf32(v.z);
            p[3] = f32_to_tf32(v.w);
        }
        #pragma unroll
        for (int i = 0; i < 4; i++) {
            int f = tid + i * 256;
            int row = f >> 5;
            int c4  = (f & 31) * 4;
            float4 v = *(const float4*)(B + (size_t)(k0g + row) * N_HID + c4);
            uint32_t* p = &Bs[row * B_STRIDE + c4];
            p[0] = f32_to_tf32(v.x);
            p[1] = f32_to_tf32(v.y);
            p[2] = f32_to_tf32(v.z);
            p[3] = f32_to_tf32(v.w);
        }
        __syncthreads();

        #pragma unroll
        for (int ks = 0; ks < 4; ks++) {
            const int k0 = ks * 8;
            uint32_t a[2][4];
            #pragma unroll
            for (int mt = 0; mt < 2; mt++) {
                int r = rbase + mt * 16 + qrow;
                a[mt][0] = As[(r    ) * A_STRIDE + k0 + qcol    ];
                a[mt][1] = As[(r + 8) * A_STRIDE + k0 + qcol    ];
                a[mt][2] = As[(r    ) * A_STRIDE + k0 + qcol + 4];
                a[mt][3] = As[(r + 8) * A_STRIDE + k0 + qcol + 4];
            }
            uint32_t b[8][2];
            #pragma unroll
            for (int nt = 0; nt < 8; nt++) {
                int c = nbase + nt * 8 + qrow;
                b[nt][0] = Bs[(k0 + qcol    ) * B_STRIDE + c];
                b[nt][1] = Bs[(k0 + qcol + 4) * B_STRIDE + c];
            }
            #pragma unroll
            for (int mt = 0; mt < 2; mt++)
                #pragma unroll
                for (int nt = 0; nt < 8; nt++)
                    asm volatile(
                        "mma.sync.aligned.m16n8k8.row.col.f32.tf32.tf32.f32 "
                        "{%0,%1,%2,%3}, {%4,%5,%6,%7}, {%8,%9}, {%0,%1,%2,%3};"
                        : "+f"(acc[mt][nt][0]), "+f"(acc[mt][nt][1]),
                          "+f"(acc[mt][nt][2]), "+f"(acc[mt][nt][3])
                        : "r"(a[mt][0]), "r"(a[mt][1]), "r"(a[mt][2]), "r"(a[mt][3]),
                          "r"(b[nt][0]), "r"(b[nt][1]));
        }
        __syncthreads();
    }

    #pragma unroll
    for (int mt = 0; mt < 2; mt++) {
        int row0 = m0 + rbase + mt * 16 + qrow;
        #pragma unroll
        for (int nt = 0; nt < 8; nt++) {
            int col = nbase + nt * 8 + 2 * qcol;
            if (row0 < M_NODES)
                *(__half2*)(C + (size_t)row0 * N_HID + col) =
                    __floats2half2_rn(acc[mt][nt][0], acc[mt][nt][1]);
            if (row0 + 8 < M_NODES)
                *(__half2*)(C + (size_t)(row0 + 8) * N_HID + col) =
                    __floats2half2_rn(acc[mt][nt][2], acc[mt][nt][3]);
        }
    }
}

// ---------------------------------------------------------------------------
// Binning kernels: build dst-sorted edge list
// ---------------------------------------------------------------------------
__global__ __launch_bounds__(256) void count_kernel(
    const int* __restrict__ edge_index)
{
    int e = blockIdx.x * blockDim.x + threadIdx.x;
    if (e >= NUM_EDGES) return;
    int dst = __ldg(edge_index + NUM_EDGES + e);
    atomicAdd(&g_deg[dst], 1);
}

__global__ __launch_bounds__(256) void scan1_kernel()
{
    __shared__ int sh[256];
    int i = blockIdx.x * 256 + threadIdx.x;
    int v = (i < M_NODES) ? g_deg[i] : 0;
    sh[threadIdx.x] = v;
    __syncthreads();
    #pragma unroll
    for (int off = 1; off < 256; off <<= 1) {
        int t = (threadIdx.x >= off) ? sh[threadIdx.x - off] : 0;
        __syncthreads();
        sh[threadIdx.x] += t;
        __syncthreads();
    }
    if (i < M_NODES) g_start[i] = sh[threadIdx.x] - v;
    if (threadIdx.x == 255) g_bsum[blockIdx.x] = sh[255];
}

__global__ __launch_bounds__(256) void scan2_kernel()
{
    __shared__ int sh[256];
    int v = (threadIdx.x < SCAN_NB) ? g_bsum[threadIdx.x] : 0;
    sh[threadIdx.x] = v;
    __syncthreads();
    #pragma unroll
    for (int off = 1; off < 256; off <<= 1) {
        int t = (threadIdx.x >= off) ? sh[threadIdx.x - off] : 0;
        __syncthreads();
        sh[threadIdx.x] += t;
        __syncthreads();
    }
    if (threadIdx.x < SCAN_NB) g_bsum[threadIdx.x] = sh[threadIdx.x] - v;
}

__global__ __launch_bounds__(256) void scan3_kernel()
{
    int i = blockIdx.x * 256 + threadIdx.x;
    if (i >= M_NODES) return;
    int s = g_start[i] + g_bsum[blockIdx.x];
    g_start[i]  = s;
    g_cursor[i] = s;
}

__global__ __launch_bounds__(256) void permute_kernel(
    const int* __restrict__ edge_index,
    const float* __restrict__ edge_weight)
{
    int e = blockIdx.x * blockDim.x + threadIdx.x;
    if (e >= NUM_EDGES) return;
    int src = __ldg(edge_index + e);
    int dst = __ldg(edge_index + NUM_EDGES + e);
    float w = __ldg(edge_weight + e);
    int p = atomicAdd(&g_cursor[dst], 1);
    g_edge[p] = make_int2(src, __float_as_int(w));
}

// ---------------------------------------------------------------------------
// Aggregate + bias + relu + log_softmax, fused. One warp per dst row.
// Lane l owns hid channels [4l, 4l+4) (8 bytes of fp16). Edge records batched
// 32-wide (coalesced int2), shuffle-broadcast; gathers are coalesced 256B/edge.
// ---------------------------------------------------------------------------
__global__ __launch_bounds__(256) void aggregate_kernel(
    const __half* __restrict__ support,
    const float* __restrict__ bias,
    float* __restrict__ out)
{
    int row  = blockIdx.x * 8 + (threadIdx.x >> 5);
    int lane = threadIdx.x & 31;
    if (row >= M_NODES) return;

    int start = g_start[row];
    int deg   = g_deg[row];
    int end   = start + deg;

    float4 acc = make_float4(0.f, 0.f, 0.f, 0.f);

    for (int base = start; base < end; base += 32) {
        int n = end - base;
        if (n > 32) n = 32;
        int   s = 0;
        float w = 0.f;
        if (lane < n) {
            int2 r = __ldg(g_edge + base + lane);
            s = r.x;
            w = __int_as_float(r.y);
        }
        for (int k = 0; k < n; k++) {
            int   sk = __shfl_sync(0xFFFFFFFF, s, k);
            float wk = __shfl_sync(0xFFFFFFFF, w, k);
            uint2 raw = __ldg((const uint2*)(support + (size_t)sk * N_HID) + lane);
            __half2 h0 = *(__half2*)&raw.x;
            __half2 h1 = *(__half2*)&raw.y;
            float2 f0 = __half22float2(h0);
            float2 f1 = __half22float2(h1);
            acc.x = fmaf(f0.x, wk, acc.x);
            acc.y = fmaf(f0.y, wk, acc.y);
            acc.z = fmaf(f1.x, wk, acc.z);
            acc.w = fmaf(f1.y, wk, acc.w);
        }
    }

    float4 b = *(const float4*)(bias + lane * 4);
    acc.x = fmaxf(acc.x + b.x, 0.f);
    acc.y = fmaxf(acc.y + b.y, 0.f);
    acc.z = fmaxf(acc.z + b.z, 0.f);
    acc.w = fmaxf(acc.w + b.w, 0.f);

    float m = fmaxf(fmaxf(acc.x, acc.y), fmaxf(acc.z, acc.w));
    #pragma unroll
    for (int off = 16; off > 0; off >>= 1)
        m = fmaxf(m, __shfl_xor_sync(0xFFFFFFFF, m, off));

    float ssum = __expf(acc.x - m) + __expf(acc.y - m) +
                 __expf(acc.z - m) + __expf(acc.w - m);
    #pragma unroll
    for (int off = 16; off > 0; off >>= 1)
        ssum += __shfl_xor_sync(0xFFFFFFFF, ssum, off);

    float lse = m + __logf(ssum);
    float4 r = make_float4(acc.x - lse, acc.y - lse, acc.z - lse, acc.w - lse);
    *(float4*)(out + (size_t)row * N_HID + lane * 4) = r;
}

// ---------------------------------------------------------------------------
extern "C" void kernel_launch(void* const* d_in, const int* in_sizes, int n_in,
                              void* d_out, int out_size)
{
    const float* x      = (const float*)d_in[0];
    const float* weight = (const float*)d_in[1];
    const float* bias   = (const float*)d_in[2];
    const int*   eidx   = (const int*)  d_in[3];
    const float* ew     = (const float*)d_in[4];
    float* out = (float*)d_out;

    __half* support;
    cudaGetSymbolAddress((void**)&support, g_support);
    void* degp;
    cudaGetSymbolAddress(&degp, g_deg);

    const int EB = (NUM_EDGES + 255) / 256;

    // GEMM (tf32 tensor cores, fp16 output)
    gemm_tf32_kernel<<<(M_NODES + 127) / 128, 256>>>(x, weight, support);

    // Binning pipeline
    cudaMemsetAsync(degp, 0, M_NODES * sizeof(int));
    count_kernel<<<EB, 256>>>(eidx);
    scan1_kernel<<<SCAN_NB, 256>>>();
    scan2_kernel<<<1, 256>>>();
    scan3_kernel<<<SCAN_NB, 256>>>();
    permute_kernel<<<EB, 256>>>(eidx, ew);

    // Fused aggregate + bias + relu + log_softmax
    aggregate_kernel<<<(M_NODES + 7) / 8, 256>>>(support, bias, out);
}